// round 8
// baseline (speedup 1.0000x reference)
#include <cuda_runtime.h>
#include <math.h>

#define T1V 257
#define BATCH 512
#define SDV 128
#define ADV 32
#define HSV 512
#define SFV 256
#define R2 131072    // 256*512 rows
#define RALL 131584  // 257*512 rows

// ---------------- scratch (__device__ globals; no runtime allocation) ----------------
__device__ float g_feats [(size_t)T1V * BATCH * HSV];       // 257x512x512
__device__ float g_xw    [(size_t)RALL * 1024];             // feats@Wih0^T + bih0
__device__ float g_outs  [(size_t)T1V * BATCH * SFV];       // h1 history (257 slots)
__device__ float g_h0hist[(size_t)(T1V + 1) * BATCH * SFV]; // h0 history, slot0 = zeros
__device__ float g_pred  [(size_t)256 * BATCH * SFV];
__device__ float g_hidA  [(size_t)R2 * HSV];
__device__ float g_hidB  [(size_t)R2 * HSV];
__device__ float g_c0    [BATCH * SFV];
__device__ float g_c1    [BATCH * SFV];
__device__ float g_pfl   [2048];
__device__ float g_pil   [512];

__device__ __forceinline__ float sigmoidf_(float x) { return 1.0f / (1.0f + expf(-x)); }

// ---------------- init: zero c0,c1 and h0hist slot 0 ----------------
__global__ void init_kernel() {
    int i = blockIdx.x * blockDim.x + threadIdx.x;  // 131072
    g_c0[i] = 0.f; g_c1[i] = 0.f;
    g_h0hist[i] = 0.f;
}

// ---------------- barrier-free LSTM step core ----------------
// smem: as[256][36] (k-major A, masked) + ws[256][68] (k-major W, col = unit_local*4 + gate)
// CTA: 128 threads, tile 32 batch x 16 units x 4 gates. Microtile 4b x 4gates(1 unit).
#define AS_STRIDE 36
#define WS_STRIDE 68
#define AS_FLOATS (256 * AS_STRIDE)   // 9216
#define SMEM_FLOATS (AS_FLOATS + 256 * WS_STRIDE)  // 9216 + 17408 = 26624

__device__ __forceinline__ void stage_tile(
    const float* __restrict__ A, const float* __restrict__ W,
    int b0, int u0, const int* __restrict__ done, bool use_mask,
    float* __restrict__ as, float* __restrict__ ws, int tid)
{
    // A: 32 rows x 256 k  -> thread: row tid>>2, k-quarter (tid&3)*64
    {
        const int r = tid >> 2;
        const int kp = (tid & 3) << 6;
        const float m = use_mask ? (1.f - (float)done[b0 + r]) : 1.f;
        const float4* src = (const float4*)(A + (size_t)(b0 + r) * SFV + kp);
#pragma unroll
        for (int q = 0; q < 16; q++) {
            float4 v = src[q];
            int k = kp + (q << 2);
            as[(k + 0) * AS_STRIDE + r] = v.x * m;
            as[(k + 1) * AS_STRIDE + r] = v.y * m;
            as[(k + 2) * AS_STRIDE + r] = v.z * m;
            as[(k + 3) * AS_STRIDE + r] = v.w * m;
        }
    }
    // W: 64 rows (16 units x 4 gates) x 256 k -> thread: dest-col tid>>1, k-half (tid&1)*128
    {
        const int wr = tid >> 1;                     // dest col = unit_local*4 + gate
        const int kp = (tid & 1) << 7;
        const int n = ((wr & 3) << 8) + u0 + (wr >> 2);  // gate*256 + unit
        const float4* src = (const float4*)(W + (size_t)n * SFV + kp);
#pragma unroll
        for (int q = 0; q < 32; q++) {
            float4 v = src[q];
            int k = kp + (q << 2);
            ws[(k + 0) * WS_STRIDE + wr] = v.x;
            ws[(k + 1) * WS_STRIDE + wr] = v.y;
            ws[(k + 2) * WS_STRIDE + wr] = v.z;
            ws[(k + 3) * WS_STRIDE + wr] = v.w;
        }
    }
}

__device__ __forceinline__ void compute256(
    float acc[4][4], const float* __restrict__ as, const float* __restrict__ ws,
    int bi, int ni)
{
    const float* ap = as + (bi << 2);
    const float* wp = ws + (ni << 2);
#pragma unroll 8
    for (int k = 0; k < 256; k++) {
        float4 a = *(const float4*)(ap + k * AS_STRIDE);
        float4 w = *(const float4*)(wp + k * WS_STRIDE);
        acc[0][0] += a.x * w.x; acc[0][1] += a.x * w.y; acc[0][2] += a.x * w.z; acc[0][3] += a.x * w.w;
        acc[1][0] += a.y * w.x; acc[1][1] += a.y * w.y; acc[1][2] += a.y * w.z; acc[1][3] += a.y * w.w;
        acc[2][0] += a.z * w.x; acc[2][1] += a.z * w.y; acc[2][2] += a.z * w.z; acc[2][3] += a.z * w.w;
        acc[3][0] += a.w * w.x; acc[3][1] += a.w * w.y; acc[3][2] += a.w * w.z; acc[3][3] += a.w * w.w;
    }
}

// merged launch: blocks 0..255 -> layer0 step s0; blocks 256..511 -> layer1 step s1.
__global__ __launch_bounds__(128, 2) void lstm_step3(
    int s0, int s1,
    float* __restrict__ h0hist,          // 258 slots
    const float* __restrict__ xw,
    float* __restrict__ outs,            // 257 slots
    float* __restrict__ c0, float* __restrict__ c1,
    const float* __restrict__ Whh0, const float* __restrict__ bhh0,
    const float* __restrict__ Wih1, const float* __restrict__ Whh1,
    const float* __restrict__ bih1, const float* __restrict__ bhh1,
    const int* __restrict__ dones,
    float* __restrict__ hid)
{
    extern __shared__ float sh[];
    float* as = sh;
    float* ws = sh + AS_FLOATS;

    const bool isL1 = (blockIdx.x >= 256);
    const int step = isL1 ? s1 : s0;
    if (step < 0) return;
    const int blk = blockIdx.x & 255;
    const int b0 = (blk >> 4) << 5;     // batch tile of 32
    const int u0 = (blk & 15) << 4;     // unit tile of 16
    const int tid = threadIdx.x;
    const int bi = tid >> 4, ni = tid & 15;
    const int* done = dones + (size_t)step * BATCH;

    float acc[4][4];
#pragma unroll
    for (int i = 0; i < 4; i++)
#pragma unroll
        for (int g = 0; g < 4; g++) acc[i][g] = 0.f;

    if (!isL1) {
        stage_tile(h0hist + (size_t)s0 * 131072, Whh0, b0, u0, done, true, as, ws, tid);
        __syncthreads();
        compute256(acc, as, ws, bi, ni);
    } else {
        stage_tile(h0hist + (size_t)(s1 + 1) * 131072, Wih1, b0, u0, done, false, as, ws, tid);
        __syncthreads();
        compute256(acc, as, ws, bi, ni);
        __syncthreads();
        const float* h1in = (s1 == 0) ? h0hist /*slot0 zeros*/ : outs + (size_t)(s1 - 1) * 131072;
        stage_tile(h1in, Whh1, b0, u0, done, true, as, ws, tid);
        __syncthreads();
        compute256(acc, as, ws, bi, ni);
    }

    // epilogue: thread owns 4 batches x 1 unit (all 4 gates local)
    const int u = u0 + ni;
    float bb[4];
#pragma unroll
    for (int g = 0; g < 4; g++)
        bb[g] = isL1 ? (bih1[(g << 8) + u] + bhh1[(g << 8) + u]) : bhh0[(g << 8) + u];

    float* cst = isL1 ? c1 : c0;
    float* hw  = isL1 ? (outs + (size_t)s1 * 131072)
                      : (h0hist + (size_t)(s0 + 1) * 131072);
    float* hh = nullptr; float* hc = nullptr;
    if (!isL1 && s0 == 256) { hh = hid;          hc = hid + 262144; }
    if ( isL1 && s1 == 256) { hh = hid + 131072; hc = hid + 393216; }

#pragma unroll
    for (int i = 0; i < 4; i++) {
        const int b = b0 + (bi << 2) + i;
        float x0 = 0.f, x1 = 0.f, x2 = 0.f, x3 = 0.f;
        if (!isL1) {
            const float* xr = xw + (size_t)s0 * 524288 + (size_t)b * 1024 + u;
            x0 = xr[0]; x1 = xr[256]; x2 = xr[512]; x3 = xr[768];
        }
        float ig = sigmoidf_(acc[i][0] + bb[0] + x0);
        float fg = sigmoidf_(acc[i][1] + bb[1] + x1);
        float gg = tanhf(acc[i][2] + bb[2] + x2);
        float og = sigmoidf_(acc[i][3] + bb[3] + x3);
        float m = 1.f - (float)done[b];
        const int idx = b * SFV + u;
        float c2 = fg * (cst[idx] * m) + ig * gg;
        float h2 = og * tanhf(c2);
        cst[idx] = c2;
        hw[idx] = h2;
        if (hh) { hh[idx] = h2; hc[idx] = c2; }
    }
}

// ---------------- generic SGEMM: C = act(A @ W^T + bias) ----------------
#define KC 16
template <int ACT>
__global__ __launch_bounds__(256) void gemm_kernel(
    const float* __restrict__ A1, int K1,
    const float* __restrict__ A2,
    const float* __restrict__ W,
    const float* __restrict__ bias,
    float* __restrict__ C,
    int M, int N, int K)
{
    __shared__ float as_[KC][132];
    __shared__ float bs_[KC][132];
    const int m0 = blockIdx.x * 128;
    const int n0 = blockIdx.y * 128;
    const int tid = threadIdx.x;
    const int mi = tid >> 4;
    const int ni = tid & 15;
    const int lrow = tid >> 2;
    const int lk = (tid & 3) * 4;

    float acc[8][8];
#pragma unroll
    for (int i = 0; i < 8; i++)
#pragma unroll
        for (int j = 0; j < 8; j++) acc[i][j] = 0.f;

    for (int kc = 0; kc < K; kc += KC) {
        const float* Asrc;
        int Ak, koff;
        if (kc < K1) { Asrc = A1; Ak = K1; koff = kc; }
        else         { Asrc = A2; Ak = K - K1; koff = kc - K1; }
#pragma unroll
        for (int r = 0; r < 2; r++) {
            int row = lrow + r * 64;
            float4 v = *(const float4*)(Asrc + (size_t)(m0 + row) * Ak + koff + lk);
            as_[lk + 0][row] = v.x; as_[lk + 1][row] = v.y;
            as_[lk + 2][row] = v.z; as_[lk + 3][row] = v.w;
            float4 w = *(const float4*)(W + (size_t)(n0 + row) * K + kc + lk);
            bs_[lk + 0][row] = w.x; bs_[lk + 1][row] = w.y;
            bs_[lk + 2][row] = w.z; bs_[lk + 3][row] = w.w;
        }
        __syncthreads();
#pragma unroll
        for (int k = 0; k < KC; k++) {
            float4 a0 = *(const float4*)&as_[k][mi * 8];
            float4 a1 = *(const float4*)&as_[k][mi * 8 + 4];
            float a[8] = {a0.x, a0.y, a0.z, a0.w, a1.x, a1.y, a1.z, a1.w};
            float b[8];
#pragma unroll
            for (int j = 0; j < 8; j++) b[j] = bs_[k][ni + j * 16];
#pragma unroll
            for (int i = 0; i < 8; i++)
#pragma unroll
                for (int j = 0; j < 8; j++) acc[i][j] += a[i] * b[j];
        }
        __syncthreads();
    }
#pragma unroll
    for (int i = 0; i < 8; i++) {
        int row = m0 + mi * 8 + i;
#pragma unroll
        for (int j = 0; j < 8; j++) {
            int col = n0 + ni + j * 16;
            float v = acc[i][j] + bias[col];
            if (ACT == 1) v = fmaxf(v, 0.f);
            C[(size_t)row * N + col] = v;
        }
    }
}

// ---------------- forward loss + intrinsic reward ----------------
__global__ void floss_kernel(const float* __restrict__ pred, const float* __restrict__ outs,
                             float* __restrict__ intr, float* __restrict__ pfl)
{
    const int w = threadIdx.x >> 5, lane = threadIdx.x & 31;
    const int r0 = blockIdx.x * 64;
    __shared__ float sred[8];
    float wacc = 0.f;
    for (int p = 0; p < 8; p++) {
        int r = r0 + p * 8 + w;
        const float4* pp = (const float4*)(pred + (size_t)r * SFV) + lane * 2;
        const float4* np = (const float4*)(outs + (size_t)(r + BATCH) * SFV) + lane * 2;
        float4 p0 = pp[0], p1 = pp[1], n0 = np[0], n1 = np[1];
        float d0 = p0.x - n0.x, d1 = p0.y - n0.y, d2 = p0.z - n0.z, d3 = p0.w - n0.w;
        float d4 = p1.x - n1.x, d5 = p1.y - n1.y, d6 = p1.z - n1.z, d7 = p1.w - n1.w;
        float s = d0 * d0 + d1 * d1 + d2 * d2 + d3 * d3 + d4 * d4 + d5 * d5 + d6 * d6 + d7 * d7;
#pragma unroll
        for (int o = 16; o; o >>= 1) s += __shfl_xor_sync(0xffffffffu, s, o);
        if (lane == 0) { intr[r] = s; wacc += s; }
    }
    if (lane == 0) sred[w] = wacc;
    __syncthreads();
    if (threadIdx.x == 0) {
        float t = 0.f;
        for (int i = 0; i < 8; i++) t += sred[i];
        pfl[blockIdx.x] = t;
    }
}

// ---------------- inverse head: mu/std + NLL partials ----------------
__global__ void inv_kernel(const float* __restrict__ hm, const float* __restrict__ hs,
                           const float* __restrict__ Wm2, const float* __restrict__ bm2,
                           const float* __restrict__ Ws2, const float* __restrict__ bs2,
                           const float* __restrict__ act, float* __restrict__ pil)
{
    extern __shared__ float sh[];
    float* wm = sh;
    float* ws2s = sh + 16384;
    float* bm = sh + 32768;
    float* bs = sh + 32800;
    float* red = sh + 32832;
    const int tid = threadIdx.x;
    for (int idx = tid; idx < 16384; idx += 256) {
        int d = idx & 31, k = idx >> 5;
        wm[idx] = Wm2[(size_t)d * HSV + k];
        ws2s[idx] = Ws2[(size_t)d * HSV + k];
    }
    if (tid < 32) { bm[tid] = bm2[tid]; bs[tid] = bs2[tid]; }
    __syncthreads();

    const int w = tid >> 5, lane = tid & 31;
    const int r0 = blockIdx.x * 256;
    float ilacc = 0.f;
    for (int p = 0; p < 32; p++) {
        int r = r0 + p * 8 + w;
        const float4* h4m = (const float4*)(hm + (size_t)r * HSV);
        const float4* h4s = (const float4*)(hs + (size_t)r * HSV);
        float am = 0.f, as2 = 0.f;
#pragma unroll 4
        for (int k4 = 0; k4 < 128; k4++) {
            float4 a = h4m[k4];
            float4 b = h4s[k4];
            int kb = k4 * 128 + lane;
            am  += a.x * wm[kb] + a.y * wm[kb + 32] + a.z * wm[kb + 64] + a.w * wm[kb + 96];
            as2 += b.x * ws2s[kb] + b.y * ws2s[kb + 32] + b.z * ws2s[kb + 64] + b.w * ws2s[kb + 96];
        }
        float mu = tanhf(am + bm[lane]);
        float sv = as2 + bs[lane];
        float sd = fmaxf(sv, 0.f) + log1pf(expf(-fabsf(sv)));
        float a_ = act[(size_t)r * ADV + lane];
        float z = (a_ - mu) / sd;
        ilacc += 0.5f * z * z + logf(sd) + 0.91893853320467274f;
    }
#pragma unroll
    for (int o = 16; o; o >>= 1) ilacc += __shfl_xor_sync(0xffffffffu, ilacc, o);
    if (lane == 0) red[w] = ilacc;
    __syncthreads();
    if (tid == 0) {
        float t = 0.f;
        for (int i = 0; i < 8; i++) t += red[i];
        pil[blockIdx.x] = t;
    }
}

// ---------------- final scalar reduce ----------------
__global__ void final_reduce_kernel(const float* __restrict__ pfl, const float* __restrict__ pil,
                                    float* __restrict__ out)
{
    __shared__ float s1[256], s2[256];
    int tid = threadIdx.x;
    float a = 0.f, b = 0.f;
    for (int i = tid; i < 2048; i += 256) a += pfl[i];
    for (int i = tid; i < 512; i += 256) b += pil[i];
    s1[tid] = a; s2[tid] = b;
    __syncthreads();
    for (int st = 128; st; st >>= 1) {
        if (tid < st) { s1[tid] += s1[tid + st]; s2[tid] += s2[tid + st]; }
        __syncthreads();
    }
    if (tid == 0) {
        out[0] = s1[0] / 33554432.f;
        out[1] = s2[0] / 4194304.f;
    }
}

// ---------------- host orchestration ----------------
extern "C" void kernel_launch(void* const* d_in, const int* in_sizes, int n_in,
                              void* d_out, int out_size)
{
    (void)in_sizes; (void)n_in; (void)out_size;
    const float* states = (const float*)d_in[0];
    const float* action = (const float*)d_in[1];
    const int*   dones  = (const int*)d_in[2];
    const float* Wfe = (const float*)d_in[3];
    const float* bfe = (const float*)d_in[4];
    const float* Wih0 = (const float*)d_in[5];
    const float* Whh0 = (const float*)d_in[6];
    const float* bih0 = (const float*)d_in[7];
    const float* bhh0 = (const float*)d_in[8];
    const float* Wih1 = (const float*)d_in[9];
    const float* Whh1 = (const float*)d_in[10];
    const float* bih1 = (const float*)d_in[11];
    const float* bhh1 = (const float*)d_in[12];
    const float* Wf1 = (const float*)d_in[13];
    const float* bf1 = (const float*)d_in[14];
    const float* Wf2 = (const float*)d_in[15];
    const float* bf2 = (const float*)d_in[16];
    const float* Wm1 = (const float*)d_in[17];
    const float* bm1 = (const float*)d_in[18];
    const float* Wm2 = (const float*)d_in[19];
    const float* bm2 = (const float*)d_in[20];
    const float* Ws1 = (const float*)d_in[21];
    const float* bs1 = (const float*)d_in[22];
    const float* Ws2 = (const float*)d_in[23];
    const float* bs2 = (const float*)d_in[24];
    float* out = (float*)d_out;

    float *feats, *xw, *outs, *h0hist, *pred, *hidA, *hidB, *c0, *c1, *pfl, *pil;
    cudaGetSymbolAddress((void**)&feats, g_feats);
    cudaGetSymbolAddress((void**)&xw, g_xw);
    cudaGetSymbolAddress((void**)&outs, g_outs);
    cudaGetSymbolAddress((void**)&h0hist, g_h0hist);
    cudaGetSymbolAddress((void**)&pred, g_pred);
    cudaGetSymbolAddress((void**)&hidA, g_hidA);
    cudaGetSymbolAddress((void**)&hidB, g_hidB);
    cudaGetSymbolAddress((void**)&c0, g_c0);
    cudaGetSymbolAddress((void**)&c1, g_c1);
    cudaGetSymbolAddress((void**)&pfl, g_pfl);
    cudaGetSymbolAddress((void**)&pil, g_pil);

    const int stepSmem = SMEM_FLOATS * 4;   // 106,496 B
    cudaFuncSetAttribute(inv_kernel, cudaFuncAttributeMaxDynamicSharedMemorySize, 32840 * 4);
    cudaFuncSetAttribute(lstm_step3, cudaFuncAttributeMaxDynamicSharedMemorySize, stepSmem);

    // init recurrent state
    init_kernel<<<256, 512>>>();

    // feature encoder: feats = relu(states @ Wfe^T + bfe)
    gemm_kernel<1><<<dim3(RALL / 128, HSV / 128), 256>>>(
        states, SDV, nullptr, Wfe, bfe, feats, RALL, HSV, SDV);

    // hoisted layer-0 input gates: xw = feats @ Wih0^T + bih0
    gemm_kernel<0><<<dim3(RALL / 128, 1024 / 128), 256>>>(
        feats, HSV, nullptr, Wih0, bih0, xw, RALL, 1024, HSV);

    // LSTM scan: one merged launch per step (L0 at t overlaps L1 at t-1)
    float* hid = out + 2 + 131072;
    lstm_step3<<<512, 128, stepSmem>>>(0, -1, h0hist, xw, outs, c0, c1,
        Whh0, bhh0, Wih1, Whh1, bih1, bhh1, dones, hid);
    for (int t = 1; t <= 256; t++) {
        lstm_step3<<<512, 128, stepSmem>>>(t, t - 1, h0hist, xw, outs, c0, c1,
            Whh0, bhh0, Wih1, Whh1, bih1, bhh1, dones, hid);
    }
    lstm_step3<<<512, 128, stepSmem>>>(-1, 256, h0hist, xw, outs, c0, c1,
        Whh0, bhh0, Wih1, Whh1, bih1, bhh1, dones, hid);

    // forward model
    gemm_kernel<1><<<dim3(R2 / 128, HSV / 128), 256>>>(
        outs, SFV, action, Wf1, bf1, hidA, R2, HSV, SFV + ADV);
    gemm_kernel<0><<<dim3(R2 / 128, SFV / 128), 256>>>(
        hidA, HSV, nullptr, Wf2, bf2, pred, R2, SFV, HSV);

    // forward loss + intrinsic reward
    floss_kernel<<<2048, 256>>>(pred, outs, out + 2, pfl);

    // inverse model hiddens
    gemm_kernel<1><<<dim3(R2 / 128, HSV / 128), 256>>>(
        outs, SFV, pred, Wm1, bm1, hidA, R2, HSV, 2 * SFV);
    gemm_kernel<1><<<dim3(R2 / 128, HSV / 128), 256>>>(
        outs, SFV, pred, Ws1, bs1, hidB, R2, HSV, 2 * SFV);

    // mu/std + inverse-loss partials
    inv_kernel<<<512, 256, 32840 * 4>>>(hidA, hidB, Wm2, bm2, Ws2, bs2, action, pil);

    // scalars
    final_reduce_kernel<<<1, 256>>>(pfl, pil, out);
}

// round 9
// speedup vs baseline: 1.0922x; 1.0922x over previous
#include <cuda_runtime.h>
#include <math.h>

#define T1V 257
#define BATCH 512
#define SDV 128
#define ADV 32
#define HSV 512
#define SFV 256
#define R2 131072    // 256*512 rows
#define RALL 131584  // 257*512 rows

// ---------------- scratch (__device__ globals; no runtime allocation) ----------------
__device__ float g_feats [(size_t)T1V * BATCH * HSV];       // 257x512x512
__device__ float g_xw    [(size_t)RALL * 1024];             // feats@Wih0^T + bih0
__device__ float g_outs  [(size_t)T1V * BATCH * SFV];       // h1 history (257 slots)
__device__ float g_h0hist[(size_t)(T1V + 1) * BATCH * SFV]; // h0 history, slot0 = zeros
__device__ float g_pred  [(size_t)256 * BATCH * SFV];
__device__ float g_hidA  [(size_t)R2 * HSV];
__device__ float g_hidB  [(size_t)R2 * HSV];
__device__ float g_c0    [BATCH * SFV];
__device__ float g_c1    [BATCH * SFV];
__device__ float g_pfl   [2048];
__device__ float g_pil   [512];

__device__ __forceinline__ float sigmoidf_(float x) { return 1.0f / (1.0f + expf(-x)); }

// ---------------- init: zero c0,c1 and h0hist slot 0 ----------------
__global__ void init_kernel() {
    int i = blockIdx.x * blockDim.x + threadIdx.x;  // 131072
    g_c0[i] = 0.f; g_c1[i] = 0.f;
    g_h0hist[i] = 0.f;
}

// ---------------- LSTM step kernel: R1-style core, K=256 per phase ----------------
// Tile: 64 batch x 16 units (64 gate rows). grid (8,16), 256 threads.
// Thread: 4 batches x 1 unit x 4 gates. KC=16 chunks: stage -> sync -> FMA -> sync.
// TWOPH=false: one phase (A1@W1) + xw input-gates in epilogue (layer 0).
// TWOPH=true : two phases (A1@W1 unmasked, A2@W2 masked) (layer 1).
#define KCR 16
template<bool TWOPH>
__global__ __launch_bounds__(256) void lstm_stepR(
    const float* __restrict__ A1, const float* __restrict__ W1, int msk1,
    const float* __restrict__ A2, const float* __restrict__ W2,
    const float* __restrict__ xw_t,          // [512 x 1024] or null
    const float* __restrict__ b1, const float* __restrict__ b2,  // b2 nullable
    float* __restrict__ cst, float* __restrict__ h_out,
    const int* __restrict__ done,
    float* __restrict__ hh, float* __restrict__ hc)
{
    __shared__ float as_[KCR][76];
    __shared__ float ws_[KCR][76];
    __shared__ float msk[64];

    const int b0 = blockIdx.x * 64;
    const int u0 = blockIdx.y * 16;
    const int tid = threadIdx.x;
    const int ui = tid & 15;
    const int bq = tid >> 4;          // 0..15
    const int lrow = tid >> 2;        // 0..63
    const int lk = (tid & 3) * 4;

    if (tid < 64) msk[tid] = 1.f - (float)done[b0 + tid];
    __syncthreads();                  // msk visible before masked staging

    float acc[4][4];
#pragma unroll
    for (int i = 0; i < 4; i++)
#pragma unroll
        for (int g = 0; g < 4; g++) acc[i][g] = 0.f;

    const int wrow = ((lrow >> 4) << 8) + u0 + (lrow & 15);  // gate*256 + unit

    // ---- phase 1: A1 @ W1^T (optionally masked)
    {
        const float mrow = msk1 ? msk[lrow] : 1.f;
        const float* xr = A1 + (size_t)(b0 + lrow) * SFV;
        const float* wr = W1 + (size_t)wrow * SFV;
        for (int kc = 0; kc < SFV; kc += KCR) {
            float4 xv = *(const float4*)(xr + kc + lk);
            float4 wv = *(const float4*)(wr + kc + lk);
            as_[lk + 0][lrow] = xv.x * mrow; as_[lk + 1][lrow] = xv.y * mrow;
            as_[lk + 2][lrow] = xv.z * mrow; as_[lk + 3][lrow] = xv.w * mrow;
            ws_[lk + 0][lrow] = wv.x; ws_[lk + 1][lrow] = wv.y;
            ws_[lk + 2][lrow] = wv.z; ws_[lk + 3][lrow] = wv.w;
            __syncthreads();
#pragma unroll
            for (int k = 0; k < KCR; k++) {
                float4 a4 = *(const float4*)&as_[k][bq << 2];
                float w0 = ws_[k][ui], w1 = ws_[k][16 + ui];
                float w2 = ws_[k][32 + ui], w3 = ws_[k][48 + ui];
                acc[0][0] += a4.x * w0; acc[0][1] += a4.x * w1; acc[0][2] += a4.x * w2; acc[0][3] += a4.x * w3;
                acc[1][0] += a4.y * w0; acc[1][1] += a4.y * w1; acc[1][2] += a4.y * w2; acc[1][3] += a4.y * w3;
                acc[2][0] += a4.z * w0; acc[2][1] += a4.z * w1; acc[2][2] += a4.z * w2; acc[2][3] += a4.z * w3;
                acc[3][0] += a4.w * w0; acc[3][1] += a4.w * w1; acc[3][2] += a4.w * w2; acc[3][3] += a4.w * w3;
            }
            __syncthreads();
        }
    }
    // ---- phase 2 (L1 only): A2 @ W2^T, masked
    if (TWOPH) {
        const float mrow = msk[lrow];
        const float* hr = A2 + (size_t)(b0 + lrow) * SFV;
        const float* wr = W2 + (size_t)wrow * SFV;
        for (int kc = 0; kc < SFV; kc += KCR) {
            float4 hv = *(const float4*)(hr + kc + lk);
            float4 wv = *(const float4*)(wr + kc + lk);
            as_[lk + 0][lrow] = hv.x * mrow; as_[lk + 1][lrow] = hv.y * mrow;
            as_[lk + 2][lrow] = hv.z * mrow; as_[lk + 3][lrow] = hv.w * mrow;
            ws_[lk + 0][lrow] = wv.x; ws_[lk + 1][lrow] = wv.y;
            ws_[lk + 2][lrow] = wv.z; ws_[lk + 3][lrow] = wv.w;
            __syncthreads();
#pragma unroll
            for (int k = 0; k < KCR; k++) {
                float4 a4 = *(const float4*)&as_[k][bq << 2];
                float w0 = ws_[k][ui], w1 = ws_[k][16 + ui];
                float w2 = ws_[k][32 + ui], w3 = ws_[k][48 + ui];
                acc[0][0] += a4.x * w0; acc[0][1] += a4.x * w1; acc[0][2] += a4.x * w2; acc[0][3] += a4.x * w3;
                acc[1][0] += a4.y * w0; acc[1][1] += a4.y * w1; acc[1][2] += a4.y * w2; acc[1][3] += a4.y * w3;
                acc[2][0] += a4.z * w0; acc[2][1] += a4.z * w1; acc[2][2] += a4.z * w2; acc[2][3] += a4.z * w3;
                acc[3][0] += a4.w * w0; acc[3][1] += a4.w * w1; acc[3][2] += a4.w * w2; acc[3][3] += a4.w * w3;
            }
            __syncthreads();
        }
    }

    // ---- epilogue: gates -> cell update (thread-local: 4 batches x 1 unit x 4 gates)
    const int u = u0 + ui;
    float bsum[4];
#pragma unroll
    for (int g = 0; g < 4; g++)
        bsum[g] = b1[(g << 8) + u] + (b2 ? b2[(g << 8) + u] : 0.f);

#pragma unroll
    for (int i = 0; i < 4; i++) {
        const int bl = (bq << 2) + i;
        const int b = b0 + bl;
        float x0 = 0.f, x1 = 0.f, x2 = 0.f, x3 = 0.f;
        if (!TWOPH) {
            const float* xr2 = xw_t + (size_t)b * 1024 + u;
            x0 = xr2[0]; x1 = xr2[256]; x2 = xr2[512]; x3 = xr2[768];
        }
        float ig = sigmoidf_(acc[i][0] + bsum[0] + x0);
        float fg = sigmoidf_(acc[i][1] + bsum[1] + x1);
        float gg = tanhf(acc[i][2] + bsum[2] + x2);
        float og = sigmoidf_(acc[i][3] + bsum[3] + x3);
        const float m = msk[bl];
        const int idx = b * SFV + u;
        float c2 = fg * (cst[idx] * m) + ig * gg;
        float h2 = og * tanhf(c2);
        cst[idx] = c2;
        h_out[idx] = h2;
        if (hh) { hh[idx] = h2; hc[idx] = c2; }
    }
}

// ---------------- generic SGEMM: C = act(A @ W^T + bias) ----------------
#define KC 16
template <int ACT>
__global__ __launch_bounds__(256) void gemm_kernel(
    const float* __restrict__ A1, int K1,
    const float* __restrict__ A2,
    const float* __restrict__ W,
    const float* __restrict__ bias,
    float* __restrict__ C,
    int M, int N, int K)
{
    __shared__ float as_[KC][132];
    __shared__ float bs_[KC][132];
    const int m0 = blockIdx.x * 128;
    const int n0 = blockIdx.y * 128;
    const int tid = threadIdx.x;
    const int mi = tid >> 4;
    const int ni = tid & 15;
    const int lrow = tid >> 2;
    const int lk = (tid & 3) * 4;

    float acc[8][8];
#pragma unroll
    for (int i = 0; i < 8; i++)
#pragma unroll
        for (int j = 0; j < 8; j++) acc[i][j] = 0.f;

    for (int kc = 0; kc < K; kc += KC) {
        const float* Asrc;
        int Ak, koff;
        if (kc < K1) { Asrc = A1; Ak = K1; koff = kc; }
        else         { Asrc = A2; Ak = K - K1; koff = kc - K1; }
#pragma unroll
        for (int r = 0; r < 2; r++) {
            int row = lrow + r * 64;
            float4 v = *(const float4*)(Asrc + (size_t)(m0 + row) * Ak + koff + lk);
            as_[lk + 0][row] = v.x; as_[lk + 1][row] = v.y;
            as_[lk + 2][row] = v.z; as_[lk + 3][row] = v.w;
            float4 w = *(const float4*)(W + (size_t)(n0 + row) * K + kc + lk);
            bs_[lk + 0][row] = w.x; bs_[lk + 1][row] = w.y;
            bs_[lk + 2][row] = w.z; bs_[lk + 3][row] = w.w;
        }
        __syncthreads();
#pragma unroll
        for (int k = 0; k < KC; k++) {
            float4 a0 = *(const float4*)&as_[k][mi * 8];
            float4 a1 = *(const float4*)&as_[k][mi * 8 + 4];
            float a[8] = {a0.x, a0.y, a0.z, a0.w, a1.x, a1.y, a1.z, a1.w};
            float b[8];
#pragma unroll
            for (int j = 0; j < 8; j++) b[j] = bs_[k][ni + j * 16];
#pragma unroll
            for (int i = 0; i < 8; i++)
#pragma unroll
                for (int j = 0; j < 8; j++) acc[i][j] += a[i] * b[j];
        }
        __syncthreads();
    }
#pragma unroll
    for (int i = 0; i < 8; i++) {
        int row = m0 + mi * 8 + i;
#pragma unroll
        for (int j = 0; j < 8; j++) {
            int col = n0 + ni + j * 16;
            float v = acc[i][j] + bias[col];
            if (ACT == 1) v = fmaxf(v, 0.f);
            C[(size_t)row * N + col] = v;
        }
    }
}

// ---------------- forward loss + intrinsic reward ----------------
__global__ void floss_kernel(const float* __restrict__ pred, const float* __restrict__ outs,
                             float* __restrict__ intr, float* __restrict__ pfl)
{
    const int w = threadIdx.x >> 5, lane = threadIdx.x & 31;
    const int r0 = blockIdx.x * 64;
    __shared__ float sred[8];
    float wacc = 0.f;
    for (int p = 0; p < 8; p++) {
        int r = r0 + p * 8 + w;
        const float4* pp = (const float4*)(pred + (size_t)r * SFV) + lane * 2;
        const float4* np = (const float4*)(outs + (size_t)(r + BATCH) * SFV) + lane * 2;
        float4 p0 = pp[0], p1 = pp[1], n0 = np[0], n1 = np[1];
        float d0 = p0.x - n0.x, d1 = p0.y - n0.y, d2 = p0.z - n0.z, d3 = p0.w - n0.w;
        float d4 = p1.x - n1.x, d5 = p1.y - n1.y, d6 = p1.z - n1.z, d7 = p1.w - n1.w;
        float s = d0 * d0 + d1 * d1 + d2 * d2 + d3 * d3 + d4 * d4 + d5 * d5 + d6 * d6 + d7 * d7;
#pragma unroll
        for (int o = 16; o; o >>= 1) s += __shfl_xor_sync(0xffffffffu, s, o);
        if (lane == 0) { intr[r] = s; wacc += s; }
    }
    if (lane == 0) sred[w] = wacc;
    __syncthreads();
    if (threadIdx.x == 0) {
        float t = 0.f;
        for (int i = 0; i < 8; i++) t += sred[i];
        pfl[blockIdx.x] = t;
    }
}

// ---------------- inverse head: mu/std + NLL partials ----------------
__global__ void inv_kernel(const float* __restrict__ hm, const float* __restrict__ hs,
                           const float* __restrict__ Wm2, const float* __restrict__ bm2,
                           const float* __restrict__ Ws2, const float* __restrict__ bs2,
                           const float* __restrict__ act, float* __restrict__ pil)
{
    extern __shared__ float sh[];
    float* wm = sh;
    float* ws2s = sh + 16384;
    float* bm = sh + 32768;
    float* bs = sh + 32800;
    float* red = sh + 32832;
    const int tid = threadIdx.x;
    for (int idx = tid; idx < 16384; idx += 256) {
        int d = idx & 31, k = idx >> 5;
        wm[idx] = Wm2[(size_t)d * HSV + k];
        ws2s[idx] = Ws2[(size_t)d * HSV + k];
    }
    if (tid < 32) { bm[tid] = bm2[tid]; bs[tid] = bs2[tid]; }
    __syncthreads();

    const int w = tid >> 5, lane = tid & 31;
    const int r0 = blockIdx.x * 256;
    float ilacc = 0.f;
    for (int p = 0; p < 32; p++) {
        int r = r0 + p * 8 + w;
        const float4* h4m = (const float4*)(hm + (size_t)r * HSV);
        const float4* h4s = (const float4*)(hs + (size_t)r * HSV);
        float am = 0.f, as2 = 0.f;
#pragma unroll 4
        for (int k4 = 0; k4 < 128; k4++) {
            float4 a = h4m[k4];
            float4 b = h4s[k4];
            int kb = k4 * 128 + lane;
            am  += a.x * wm[kb] + a.y * wm[kb + 32] + a.z * wm[kb + 64] + a.w * wm[kb + 96];
            as2 += b.x * ws2s[kb] + b.y * ws2s[kb + 32] + b.z * ws2s[kb + 64] + b.w * ws2s[kb + 96];
        }
        float mu = tanhf(am + bm[lane]);
        float sv = as2 + bs[lane];
        float sd = fmaxf(sv, 0.f) + log1pf(expf(-fabsf(sv)));
        float a_ = act[(size_t)r * ADV + lane];
        float z = (a_ - mu) / sd;
        ilacc += 0.5f * z * z + logf(sd) + 0.91893853320467274f;
    }
#pragma unroll
    for (int o = 16; o; o >>= 1) ilacc += __shfl_xor_sync(0xffffffffu, ilacc, o);
    if (lane == 0) red[w] = ilacc;
    __syncthreads();
    if (tid == 0) {
        float t = 0.f;
        for (int i = 0; i < 8; i++) t += red[i];
        pil[blockIdx.x] = t;
    }
}

// ---------------- final scalar reduce ----------------
__global__ void final_reduce_kernel(const float* __restrict__ pfl, const float* __restrict__ pil,
                                    float* __restrict__ out)
{
    __shared__ float s1[256], s2[256];
    int tid = threadIdx.x;
    float a = 0.f, b = 0.f;
    for (int i = tid; i < 2048; i += 256) a += pfl[i];
    for (int i = tid; i < 512; i += 256) b += pil[i];
    s1[tid] = a; s2[tid] = b;
    __syncthreads();
    for (int st = 128; st; st >>= 1) {
        if (tid < st) { s1[tid] += s1[tid + st]; s2[tid] += s2[tid + st]; }
        __syncthreads();
    }
    if (tid == 0) {
        out[0] = s1[0] / 33554432.f;
        out[1] = s2[0] / 4194304.f;
    }
}

// ---------------- host orchestration ----------------
extern "C" void kernel_launch(void* const* d_in, const int* in_sizes, int n_in,
                              void* d_out, int out_size)
{
    (void)in_sizes; (void)n_in; (void)out_size;
    const float* states = (const float*)d_in[0];
    const float* action = (const float*)d_in[1];
    const int*   dones  = (const int*)d_in[2];
    const float* Wfe = (const float*)d_in[3];
    const float* bfe = (const float*)d_in[4];
    const float* Wih0 = (const float*)d_in[5];
    const float* Whh0 = (const float*)d_in[6];
    const float* bih0 = (const float*)d_in[7];
    const float* bhh0 = (const float*)d_in[8];
    const float* Wih1 = (const float*)d_in[9];
    const float* Whh1 = (const float*)d_in[10];
    const float* bih1 = (const float*)d_in[11];
    const float* bhh1 = (const float*)d_in[12];
    const float* Wf1 = (const float*)d_in[13];
    const float* bf1 = (const float*)d_in[14];
    const float* Wf2 = (const float*)d_in[15];
    const float* bf2 = (const float*)d_in[16];
    const float* Wm1 = (const float*)d_in[17];
    const float* bm1 = (const float*)d_in[18];
    const float* Wm2 = (const float*)d_in[19];
    const float* bm2 = (const float*)d_in[20];
    const float* Ws1 = (const float*)d_in[21];
    const float* bs1 = (const float*)d_in[22];
    const float* Ws2 = (const float*)d_in[23];
    const float* bs2 = (const float*)d_in[24];
    float* out = (float*)d_out;

    float *feats, *xw, *outs, *h0hist, *pred, *hidA, *hidB, *c0, *c1, *pfl, *pil;
    cudaGetSymbolAddress((void**)&feats, g_feats);
    cudaGetSymbolAddress((void**)&xw, g_xw);
    cudaGetSymbolAddress((void**)&outs, g_outs);
    cudaGetSymbolAddress((void**)&h0hist, g_h0hist);
    cudaGetSymbolAddress((void**)&pred, g_pred);
    cudaGetSymbolAddress((void**)&hidA, g_hidA);
    cudaGetSymbolAddress((void**)&hidB, g_hidB);
    cudaGetSymbolAddress((void**)&c0, g_c0);
    cudaGetSymbolAddress((void**)&c1, g_c1);
    cudaGetSymbolAddress((void**)&pfl, g_pfl);
    cudaGetSymbolAddress((void**)&pil, g_pil);

    cudaFuncSetAttribute(inv_kernel, cudaFuncAttributeMaxDynamicSharedMemorySize, 32840 * 4);

    // init recurrent state (c0, c1, h0hist slot 0 = zeros)
    init_kernel<<<256, 512>>>();

    // feature encoder: feats = relu(states @ Wfe^T + bfe)
    gemm_kernel<1><<<dim3(RALL / 128, HSV / 128), 256>>>(
        states, SDV, nullptr, Wfe, bfe, feats, RALL, HSV, SDV);

    // hoisted layer-0 input gates: xw = feats @ Wih0^T + bih0
    gemm_kernel<0><<<dim3(RALL / 128, 1024 / 128), 256>>>(
        feats, HSV, nullptr, Wih0, bih0, xw, RALL, 1024, HSV);

    // LSTM scan: 2 launches per step, R1-style core, history buffers
    float* hid = out + 2 + 131072;
    dim3 lgrid(8, 16);
    for (int t = 0; t < T1V; t++) {
        const bool last = (t == T1V - 1);
        // layer 0: gates = (h0[t]*m) @ Whh0^T + xw[t]; writes h0hist[t+1]
        lstm_stepR<false><<<lgrid, 256>>>(
            h0hist + (size_t)t * 131072, Whh0, 1,
            nullptr, nullptr,
            xw + (size_t)t * 524288,
            bhh0, nullptr,
            c0, h0hist + (size_t)(t + 1) * 131072,
            dones + (size_t)t * BATCH,
            last ? hid : nullptr, last ? hid + 262144 : nullptr);
        // layer 1: gates = h0[t+1] @ Wih1^T + (h1[t-1]*m) @ Whh1^T; writes outs[t]
        lstm_stepR<true><<<lgrid, 256>>>(
            h0hist + (size_t)(t + 1) * 131072, Wih1, 0,
            (t == 0) ? h0hist /*slot0 zeros*/ : outs + (size_t)(t - 1) * 131072, Whh1,
            nullptr,
            bih1, bhh1,
            c1, outs + (size_t)t * 131072,
            dones + (size_t)t * BATCH,
            last ? hid + 131072 : nullptr, last ? hid + 393216 : nullptr);
    }

    // forward model
    gemm_kernel<1><<<dim3(R2 / 128, HSV / 128), 256>>>(
        outs, SFV, action, Wf1, bf1, hidA, R2, HSV, SFV + ADV);
    gemm_kernel<0><<<dim3(R2 / 128, SFV / 128), 256>>>(
        hidA, HSV, nullptr, Wf2, bf2, pred, R2, SFV, HSV);

    // forward loss + intrinsic reward
    floss_kernel<<<2048, 256>>>(pred, outs, out + 2, pfl);

    // inverse model hiddens
    gemm_kernel<1><<<dim3(R2 / 128, HSV / 128), 256>>>(
        outs, SFV, pred, Wm1, bm1, hidA, R2, HSV, 2 * SFV);
    gemm_kernel<1><<<dim3(R2 / 128, HSV / 128), 256>>>(
        outs, SFV, pred, Ws1, bs1, hidB, R2, HSV, 2 * SFV);

    // mu/std + inverse-loss partials
    inv_kernel<<<512, 256, 32840 * 4>>>(hidA, hidB, Wm2, bm2, Ws2, bs2, action, pil);

    // scalars
    final_reduce_kernel<<<1, 256>>>(pfl, pil, out);
}